// round 14
// baseline (speedup 1.0000x reference)
#include <cuda_runtime.h>
#include <cstdint>

// PowerSpectrum: values[S,N,L,M,Q] f32 -> out[S,N,L*Q*Q] f32
// out[s,n,l,q,p] = rsqrt(2l+1) * sum_{m<2l+1} v[m,q]*v[m,p]
// Shapes: S=4, N=2000, L=4, M=7, Q=64 -> 32000 (s,n,l) tiles.
//
// R14 (closing experiment): 256 threads per tile, 4x4 per-thread block.
// Halves per-thread regs (~40), doubles warps issuing stores per tile.
// Tests the one axis not yet isolated (threads/tile). Expected neutral
// vs R4 (88.5us, DRAM 76%); any delta >2% is signal.

#define L_DIM 4
#define M_DIM 7
#define Q_DIM 64
#define TILE_IN   (M_DIM * Q_DIM)   // 448 floats
#define TILE_OUT  (Q_DIM * Q_DIM)   // 4096 floats

template<int MM>
__device__ __forceinline__ void gram_tile(const float (*__restrict__ sv)[Q_DIM],
                                          float* __restrict__ ot, int tid)
{
    const int p0 = (tid & 15) << 2;  // 0,4,...,60
    const int q0 = (tid >> 4) << 2;  // 0,4,...,60  (16 q-groups x 4 rows)

    const float cg = rsqrtf((float)MM);

    float4 acc[4];
    #pragma unroll
    for (int r = 0; r < 4; r++) acc[r] = make_float4(0.f, 0.f, 0.f, 0.f);

    #pragma unroll
    for (int m = 0; m < MM; m++) {
        const float4 b = *(const float4*)&sv[m][p0];
        const float4 a = *(const float4*)&sv[m][q0];
        const float ar[4] = {a.x, a.y, a.z, a.w};
        #pragma unroll
        for (int r = 0; r < 4; r++) {
            acc[r].x += ar[r] * b.x;
            acc[r].y += ar[r] * b.y;
            acc[r].z += ar[r] * b.z;
            acc[r].w += ar[r] * b.w;
        }
    }

    // Streaming stores: 16 threads (same q-group) cover one full 256B
    // output row; fully coalesced. 4 independent STG.128 per thread.
    #pragma unroll
    for (int r = 0; r < 4; r++) {
        float4 o = make_float4(acc[r].x * cg, acc[r].y * cg,
                               acc[r].z * cg, acc[r].w * cg);
        __stcs((float4*)(ot + (size_t)(q0 + r) * Q_DIM + p0), o);
    }
}

__global__ __launch_bounds__(256)
void powerspectrum_kernel(const float* __restrict__ values,
                          float* __restrict__ out)
{
    const int tile = blockIdx.x;           // tile = (s*N + n)*L + l
    const int l    = tile & (L_DIM - 1);

    const float* vt = values + (size_t)tile * TILE_IN;
    float*       ot = out    + (size_t)tile * TILE_OUT;

    __shared__ float sv[M_DIM][Q_DIM];     // 1792 B

    const int tid = threadIdx.x;

    // 448 floats = 112 float4 loads; threads 0..111
    if (tid < TILE_IN / 4)
        ((float4*)&sv[0][0])[tid] = ((const float4*)vt)[tid];
    __syncthreads();

    switch (l) {
        case 0: gram_tile<1>(sv, ot, tid); break;
        case 1: gram_tile<3>(sv, ot, tid); break;
        case 2: gram_tile<5>(sv, ot, tid); break;
        default: gram_tile<7>(sv, ot, tid); break;
    }
}

extern "C" void kernel_launch(void* const* d_in, const int* in_sizes, int n_in,
                              void* d_out, int out_size)
{
    const float* values = (const float*)d_in[0];
    float* out = (float*)d_out;

    const int tiles = in_sizes[0] / TILE_IN;   // S*N*L = 32000

    powerspectrum_kernel<<<tiles, 256>>>(values, out);
}

// round 15
// speedup vs baseline: 1.2797x; 1.2797x over previous
#include <cuda_runtime.h>
#include <cstdint>

// PowerSpectrum: values[S,N,L,M,Q] f32 -> out[S,N,L*Q*Q] f32
// out[s,n,l,q,p] = rsqrt(2l+1) * sum_{m<2l+1} v[m,q]*v[m,p]
// Shapes: S=4, N=2000, L=4, M=7, Q=64 -> 32000 (s,n,l) tiles.
//
// SESSION FINAL (R4 design; 88.5us best, DRAM ~76%, HBM ~6.1TB/s --
// the device's path-independent pure-write ceiling). Full falsification
// matrix: R5 CTA merging (neutral), R6 8x8 tile (reg collapse), R8
// occupancy cap (neutral), R9 TMA bulk store (neutral), R12 persistent
// blocked CTAs (lost load/store overlap), R14 256thr/4x4 tile (store-
// MLP + LDS regression despite 88% occ). Load-bearing properties:
// 8-deep per-thread STG.128 bursts, 1.5 B LDS per FFMA, and CTA
// turnover overlapping new-tile loads with retiring-tile store drain.
//
// Design: one CTA per (s,n,l) tile. 1.8KB input to SMEM, 8x4 per-thread
// register block, compile-time m-count per l (1/3/5/7 -- invalid m rows
// never touched), streaming .cs stores (write-once output kept from
// evicting the L2-resident input), fully coalesced 256B row segments.

#define L_DIM 4
#define M_DIM 7
#define Q_DIM 64
#define TILE_IN   (M_DIM * Q_DIM)   // 448 floats
#define TILE_OUT  (Q_DIM * Q_DIM)   // 4096 floats

template<int MM>
__device__ __forceinline__ void gram_tile(const float (*__restrict__ sv)[Q_DIM],
                                          float* __restrict__ ot, int tid)
{
    const int p0 = (tid & 15) << 2;  // 0,4,...,60
    const int q0 = (tid >> 4) << 3;  // 0,8,...,56

    const float cg = rsqrtf((float)MM);

    float4 acc[8];
    #pragma unroll
    for (int r = 0; r < 8; r++) acc[r] = make_float4(0.f, 0.f, 0.f, 0.f);

    #pragma unroll
    for (int m = 0; m < MM; m++) {
        const float4 b  = *(const float4*)&sv[m][p0];
        const float4 a0 = *(const float4*)&sv[m][q0];
        const float4 a1 = *(const float4*)&sv[m][q0 + 4];
        const float ar[8] = {a0.x, a0.y, a0.z, a0.w, a1.x, a1.y, a1.z, a1.w};
        #pragma unroll
        for (int r = 0; r < 8; r++) {
            acc[r].x += ar[r] * b.x;
            acc[r].y += ar[r] * b.y;
            acc[r].z += ar[r] * b.z;
            acc[r].w += ar[r] * b.w;
        }
    }

    // Streaming stores: 16 threads (same q-group) cover one full 256B
    // output row; fully coalesced. 8 independent STG.128 per thread.
    #pragma unroll
    for (int r = 0; r < 8; r++) {
        float4 o = make_float4(acc[r].x * cg, acc[r].y * cg,
                               acc[r].z * cg, acc[r].w * cg);
        __stcs((float4*)(ot + (size_t)(q0 + r) * Q_DIM + p0), o);
    }
}

__global__ __launch_bounds__(128)
void powerspectrum_kernel(const float* __restrict__ values,
                          float* __restrict__ out)
{
    const int tile = blockIdx.x;           // tile = (s*N + n)*L + l
    const int l    = tile & (L_DIM - 1);

    const float* vt = values + (size_t)tile * TILE_IN;
    float*       ot = out    + (size_t)tile * TILE_OUT;

    __shared__ float sv[M_DIM][Q_DIM];     // 1792 B

    const int tid = threadIdx.x;

    // 448 floats = 112 float4 loads; threads 0..111
    if (tid < TILE_IN / 4)
        ((float4*)&sv[0][0])[tid] = ((const float4*)vt)[tid];
    __syncthreads();

    switch (l) {
        case 0: gram_tile<1>(sv, ot, tid); break;
        case 1: gram_tile<3>(sv, ot, tid); break;
        case 2: gram_tile<5>(sv, ot, tid); break;
        default: gram_tile<7>(sv, ot, tid); break;
    }
}

extern "C" void kernel_launch(void* const* d_in, const int* in_sizes, int n_in,
                              void* d_out, int out_size)
{
    const float* values = (const float*)d_in[0];
    float* out = (float*)d_out;

    const int tiles = in_sizes[0] / TILE_IN;   // S*N*L = 32000

    powerspectrum_kernel<<<tiles, 128>>>(values, out);
}